// round 8
// baseline (speedup 1.0000x reference)
#include <cuda_runtime.h>
#include <cuda_fp16.h>
#include <math.h>

#define NN 50000
#define FF 48
#define CC 16     // H*C1 with H=1 -> softmax == 1, attention vanishes
#define L1 8
#define NB 148    // resident blocks (<= SM count)
#define NT 1024

// ---------------- device scratch ----------------
__device__ __align__(32) __half g_yh[NN * CC];    // x @ W (fp16)
__device__ __align__(32) __half g_aggh[NN * CC];  // fp16 segment sum (self loop preloaded)
__device__ int g_degi[NN];        // in-degree; zero at load, self-cleaned each run
__device__ int g_bar_count = 0;
__device__ volatile int g_bar_phase = 0;

// software grid barrier (all NB blocks resident by construction)
__device__ __forceinline__ void grid_barrier() {
    __syncthreads();
    if (threadIdx.x == 0) {
        __threadfence();
        int ph = g_bar_phase;
        if (atomicAdd(&g_bar_count, 1) == NB - 1) {
            g_bar_count = 0;           // reset before release
            __threadfence();
            g_bar_phase = ph + 1;
        } else {
            while (g_bar_phase == ph) __nanosleep(128);
            __threadfence();
        }
    }
    __syncthreads();
}

// int64 node ids < 50000 => odd 32-bit words all zero over first 8 entries.
__device__ __forceinline__ bool detect64(const unsigned* __restrict__ ew) {
    unsigned v = 0u;
#pragma unroll
    for (int k = 0; k < 8; k++) v |= __ldg(&ew[2 * k + 1]);
    return v == 0u;
}

__device__ __forceinline__ void red_h8(__half* addr, uint4 v) {
    asm volatile("red.global.add.noftz.v4.f16x2 [%0], {%1,%2,%3,%4};"
                 :: "l"(addr), "r"(v.x), "r"(v.y), "r"(v.z), "r"(v.w) : "memory");
}

__global__ __launch_bounds__(NT, 1)
void k_fused(const float* __restrict__ x, const float* __restrict__ W,
             const void* __restrict__ ei,
             const float* __restrict__ bias,
             const float* __restrict__ l1w,   // [16,8]
             const float* __restrict__ l1b,
             const float* __restrict__ ow,    // [8,1]
             const float* __restrict__ ob,
             const float* __restrict__ labels,
             const float* __restrict__ wts,
             float* __restrict__ pout, float* __restrict__ losss,
             int n, int E, float inv_n) {
    __shared__ float sW[FF * CC];          // 3 KB
    __shared__ float sX[64 * FF];          // 12 KB : 64 node rows per chunk
    __shared__ float sHead[CC * L1 + CC + 2 * L1 + 1];
    __shared__ float wsum[32];

    const int tid = threadIdx.x;
    const bool is64 = detect64((const unsigned*)ei);

    // ---------------- phase A: projection y = x @ W ----------------
    if (blockIdx.x == 0 && tid == 0 && losss) *losss = 0.0f;
    for (int i = tid; i < FF * CC; i += NT) sW[i] = W[i];

    int nChunks = (n + 63) / 64;
    for (int ch = blockIdx.x; ch < nChunks; ch += NB) {
        int nodeBase = ch * 64;
        __syncthreads();               // protect sX reuse
        for (int i = tid; i < 64 * FF; i += NT) {
            int g = nodeBase * FF + i;
            sX[i] = (g < n * FF) ? x[g] : 0.0f;
        }
        __syncthreads();
        int node = nodeBase + (tid >> 4);
        int c    = tid & 15;
        if (node < n) {
            const float* xr = &sX[(tid >> 4) * FF];
            float acc = 0.0f;
#pragma unroll
            for (int k = 0; k < FF; k++) acc = fmaf(xr[k], sW[k * CC + c], acc);
            __half hv = __float2half(acc);
            g_yh[node * CC + c]   = hv;
            g_aggh[node * CC + c] = hv;     // self-loop contribution
        }
    }

    grid_barrier();

    // ---------------- phase B: edge scatter (2 lanes/edge) + deg histogram ----------------
    {
        const int stride = NB * NT;
        const long long items = (long long)E * 2;
        if (is64) {
            const long long* sp = (const long long*)ei;
            const long long* dp = sp + E;
            for (long long t = (long long)blockIdx.x * NT + tid; t < items; t += stride) {
                int e = (int)(t >> 1), q = (int)(t & 1);
                int src = (int)__ldg(&sp[e]);
                int dst = (int)__ldg(&dp[e]);
                uint4 v = __ldg((const uint4*)&g_yh[src * CC + q * 8]);
                red_h8(&g_aggh[dst * CC + q * 8], v);
                if (q == 0) atomicAdd(&g_degi[dst], 1);
            }
        } else {
            const int* sp = (const int*)ei;
            const int* dp = sp + E;
            for (long long t = (long long)blockIdx.x * NT + tid; t < items; t += stride) {
                int e = (int)(t >> 1), q = (int)(t & 1);
                int src = __ldg(&sp[e]);
                int dst = __ldg(&dp[e]);
                uint4 v = __ldg((const uint4*)&g_yh[src * CC + q * 8]);
                red_h8(&g_aggh[dst * CC + q * 8], v);
                if (q == 0) atomicAdd(&g_degi[dst], 1);
            }
        }
    }

    grid_barrier();

    // ---------------- phase C: head (2 lanes per node) + loss reduce ----------------
    float* sl1w = sHead;                    // [CC*L1]
    float* sb   = sHead + CC * L1;          // [CC]
    float* sl1b = sb + CC;                  // [L1]
    float* sow  = sl1b + L1;                // [L1]
    float* sob  = sow + L1;                 // [1]
    if (tid < CC * L1) sl1w[tid] = l1w[tid];
    if (tid < CC) sb[tid] = bias[tid];
    if (tid < L1) { sl1b[tid] = l1b[tid]; sow[tid] = ow[tid]; }
    if (tid == 0) sob[0] = ob[0];
    __syncthreads();

    float term = 0.0f;
    {
        long long t = (long long)blockIdx.x * NT + tid;   // stride >= 2n items
        int i = (int)(t >> 1);
        int a = (int)(t & 1);
        if (i < n) {
            int degc = __ldg(&g_degi[i]);
            float invdeg = 1.0f / (float)(degc + 1);      // + self loop
            uint4 r = *(const uint4*)&g_aggh[i * CC + a * 8];
            if (a == 0) g_degi[i] = 0;                    // reset for next replay
            float h[8];
            {
                const unsigned rr[4] = {r.x, r.y, r.z, r.w};
#pragma unroll
                for (int k = 0; k < 4; k++) {
                    float2 f = __half22float2(*(const __half2*)&rr[k]);
                    h[2 * k]     = f.x;
                    h[2 * k + 1] = f.y;
                }
            }
            int cbase = a * 8;
#pragma unroll
            for (int k = 0; k < 8; k++)
                h[k] = fmaxf(fmaf(h[k], invdeg, sb[cbase + k]), 0.0f);

            float s[L1];
#pragma unroll
            for (int j = 0; j < L1; j++) {
                float acc = 0.0f;
#pragma unroll
                for (int k = 0; k < 8; k++)
                    acc = fmaf(h[k], sl1w[(cbase + k) * L1 + j], acc);
                s[j] = acc;
            }
            float z = 0.0f;
#pragma unroll
            for (int j = 0; j < L1; j++) {
                float sj = s[j] + __shfl_xor_sync(0xFFFFFFFFu, s[j], 1);
                float h2 = fmaxf(sj + sl1b[j], 0.0f);
                z = fmaf(h2, sow[j], z);
            }
            if (a == 0) {
                z += sob[0];
                float p = 1.0f / (1.0f + __expf(-z));
                pout[i] = p;
                const float eps = 1e-7f;
                float pc = fminf(fmaxf(p, eps), 1.0f - eps);
                float sel = (labels[i] > 0.5f) ? pc : (1.0f - pc);  // labels exactly 0/1
                term = wts[i] * (-__logf(sel)) * inv_n;
            }
        }
    }
    // block reduce -> one atomic per block
#pragma unroll
    for (int off = 16; off > 0; off >>= 1)
        term += __shfl_down_sync(0xFFFFFFFFu, term, off);
    int wid = tid >> 5, lid = tid & 31;
    if (lid == 0) wsum[wid] = term;
    __syncthreads();
    if (wid == 0) {
        float s2 = (lid < (NT >> 5)) ? wsum[lid] : 0.0f;
#pragma unroll
        for (int off = 16; off > 0; off >>= 1)
            s2 += __shfl_down_sync(0xFFFFFFFFu, s2, off);
        if (lid == 0 && losss) atomicAdd(losss, s2);
    }
}

// ---------------- launch ----------------
extern "C" void kernel_launch(void* const* d_in, const int* in_sizes, int n_in,
                              void* d_out, int out_size) {
    const float* x      = (const float*)d_in[0];
    const void*  ei     = d_in[1];
    const float* labels = (const float*)d_in[2];
    const float* wts    = (const float*)d_in[3];
    const float* W      = (const float*)d_in[4];
    // d_in[5]=u, d_in[6]=c unused (H=1 softmax == 1)
    const float* bias   = (const float*)d_in[7];
    const float* l1w    = (const float*)d_in[8];
    const float* l1b    = (const float*)d_in[9];
    const float* ow     = (const float*)d_in[10];
    const float* ob     = (const float*)d_in[11];

    int n = in_sizes[0] / FF;
    int E = in_sizes[1] / 2;

    float* out = (float*)d_out;
    int loss_slot = (out_size == n + 1) ? 1 : 0;
    float* pout  = loss_slot ? (out + 1) : out;
    float* losss = loss_slot ? out : (float*)0;

    k_fused<<<NB, NT>>>(x, W, ei, bias, l1w, l1b, ow, ob, labels, wts,
                        pout, losss, n, E, 1.0f / (float)n);
}

// round 9
// speedup vs baseline: 1.0410x; 1.0410x over previous
#include <cuda_runtime.h>
#include <cuda_fp16.h>
#include <math.h>

#define NN 50000
#define FF 48
#define CC 16     // H*C1 with H=1 -> softmax == 1, attention vanishes
#define L1 8
#define NB 148    // resident blocks (<= SM count)
#define NT 1024
#define HB 48     // blocks doing the deg histogram during phase A (rest do proj)

// ---------------- device scratch ----------------
__device__ __align__(32) __half g_yh[NN * CC];    // x @ W (fp16)
__device__ __align__(32) __half g_aggh[NN * CC];  // fp16 segment sum (self loop preloaded)
__device__ int g_degi[NN];        // in-degree; zero at load, self-cleaned each run
__device__ int g_bar_count = 0;
__device__ volatile int g_bar_phase = 0;

// software grid barrier (all NB blocks resident by construction)
__device__ __forceinline__ void grid_barrier() {
    __syncthreads();
    if (threadIdx.x == 0) {
        __threadfence();
        int ph = g_bar_phase;
        if (atomicAdd(&g_bar_count, 1) == NB - 1) {
            g_bar_count = 0;           // reset before release
            __threadfence();
            g_bar_phase = ph + 1;
        } else {
            while (g_bar_phase == ph) __nanosleep(64);
            __threadfence();
        }
    }
    __syncthreads();
}

// int64 node ids < 50000 => odd 32-bit words all zero over first 8 entries.
__device__ __forceinline__ bool detect64(const unsigned* __restrict__ ew) {
    unsigned v = 0u;
#pragma unroll
    for (int k = 0; k < 8; k++) v |= __ldg(&ew[2 * k + 1]);
    return v == 0u;
}

__device__ __forceinline__ void red_h8(__half* addr, uint4 v) {
    asm volatile("red.global.add.noftz.v4.f16x2 [%0], {%1,%2,%3,%4};"
                 :: "l"(addr), "r"(v.x), "r"(v.y), "r"(v.z), "r"(v.w) : "memory");
}

__global__ __launch_bounds__(NT, 1)
void k_fused(const float* __restrict__ x, const float* __restrict__ W,
             const void* __restrict__ ei,
             const float* __restrict__ bias,
             const float* __restrict__ l1w,   // [16,8]
             const float* __restrict__ l1b,
             const float* __restrict__ ow,    // [8,1]
             const float* __restrict__ ob,
             const float* __restrict__ labels,
             const float* __restrict__ wts,
             float* __restrict__ pout, float* __restrict__ losss,
             int n, int E, float inv_n) {
    __shared__ float sW[FF * CC];          // 3 KB
    __shared__ float sX[64 * FF];          // 12 KB : 64 node rows per chunk
    __shared__ float sHead[CC * L1 + CC + 2 * L1 + 1];
    __shared__ float wsum[32];

    const int tid = threadIdx.x;
    const int bx  = blockIdx.x;
    const bool is64 = detect64((const unsigned*)ei);

    // ========== phase A: proj (blocks HB..NB-1)  ||  deg histogram (blocks 0..HB-1) ==========
    if (bx >= HB) {
        // ---- projection y = x @ W (smem-staged) ----
        if (bx == HB && tid == 0 && losss) *losss = 0.0f;
        for (int i = tid; i < FF * CC; i += NT) sW[i] = W[i];
        int nChunks = (n + 63) / 64;
        for (int ch = bx - HB; ch < nChunks; ch += NB - HB) {
            int nodeBase = ch * 64;
            __syncthreads();               // protect sX reuse
            for (int i = tid; i < 64 * FF; i += NT) {
                int g = nodeBase * FF + i;
                sX[i] = (g < n * FF) ? x[g] : 0.0f;
            }
            __syncthreads();
            int node = nodeBase + (tid >> 4);
            int c    = tid & 15;
            if (node < n) {
                const float* xr = &sX[(tid >> 4) * FF];
                float acc = 0.0f;
#pragma unroll
                for (int k = 0; k < FF; k++) acc = fmaf(xr[k], sW[k * CC + c], acc);
                __half hv = __float2half(acc);
                g_yh[node * CC + c]   = hv;
                g_aggh[node * CC + c] = hv;     // self-loop contribution
            }
        }
    } else {
        // ---- dst in-degree histogram (LTS-bound; overlaps with proj's FMA work) ----
        const int stride = HB * NT;
        if (is64) {
            const long long* dp = (const long long*)ei + E;
            for (int e = bx * NT + tid; e < E; e += stride)
                atomicAdd(&g_degi[(int)__ldg(&dp[e])], 1);
        } else {
            const int* dp = (const int*)ei + E;
            for (int e = bx * NT + tid; e < E; e += stride)
                atomicAdd(&g_degi[__ldg(&dp[e])], 1);
        }
    }

    grid_barrier();

    // ========== phase B: edge scatter, 2 lanes/edge, unrolled x2 ==========
    {
        const long long stride = (long long)NB * NT;   // even -> q is loop-invariant
        const long long items  = (long long)E * 2;
        const long long t0     = (long long)bx * NT + tid;
        const int qo = ((int)(t0 & 1)) * 8;
        if (is64) {
            const long long* sp = (const long long*)ei;
            const long long* dp = sp + E;
            for (long long t = t0; t < items; t += 2 * stride) {
                long long t1 = t + stride;
                int e0 = (int)(t >> 1);
                int e1 = (int)(t1 >> 1);
                bool h1 = t1 < items;
                int s0 = (int)__ldg(&sp[e0]);
                int d0 = (int)__ldg(&dp[e0]);
                int s1 = 0, d1 = 0;
                if (h1) { s1 = (int)__ldg(&sp[e1]); d1 = (int)__ldg(&dp[e1]); }
                uint4 y0 = __ldg((const uint4*)&g_yh[s0 * CC + qo]);
                uint4 y1 = __ldg((const uint4*)&g_yh[s1 * CC + qo]);
                red_h8(&g_aggh[d0 * CC + qo], y0);
                if (h1) red_h8(&g_aggh[d1 * CC + qo], y1);
            }
        } else {
            const int* sp = (const int*)ei;
            const int* dp = sp + E;
            for (long long t = t0; t < items; t += 2 * stride) {
                long long t1 = t + stride;
                int e0 = (int)(t >> 1);
                int e1 = (int)(t1 >> 1);
                bool h1 = t1 < items;
                int s0 = __ldg(&sp[e0]);
                int d0 = __ldg(&dp[e0]);
                int s1 = 0, d1 = 0;
                if (h1) { s1 = __ldg(&sp[e1]); d1 = __ldg(&dp[e1]); }
                uint4 y0 = __ldg((const uint4*)&g_yh[s0 * CC + qo]);
                uint4 y1 = __ldg((const uint4*)&g_yh[s1 * CC + qo]);
                red_h8(&g_aggh[d0 * CC + qo], y0);
                if (h1) red_h8(&g_aggh[d1 * CC + qo], y1);
            }
        }
    }

    grid_barrier();

    // ========== phase C: head (2 lanes per node) + loss reduce ==========
    float* sl1w = sHead;                    // [CC*L1]
    float* sb   = sHead + CC * L1;          // [CC]
    float* sl1b = sb + CC;                  // [L1]
    float* sow  = sl1b + L1;                // [L1]
    float* sob  = sow + L1;                 // [1]
    if (tid < CC * L1) sl1w[tid] = l1w[tid];
    if (tid < CC) sb[tid] = bias[tid];
    if (tid < L1) { sl1b[tid] = l1b[tid]; sow[tid] = ow[tid]; }
    if (tid == 0) sob[0] = ob[0];
    __syncthreads();

    float term = 0.0f;
    {
        long long t = (long long)bx * NT + tid;   // NB*NT >= 2n
        int i = (int)(t >> 1);
        int a = (int)(t & 1);
        if (i < n) {
            int degc = __ldg(&g_degi[i]);
            float invdeg = 1.0f / (float)(degc + 1);      // + self loop
            uint4 r = *(const uint4*)&g_aggh[i * CC + a * 8];
            if (a == 0) g_degi[i] = 0;                    // reset for next replay
            float h[8];
            {
                const unsigned rr[4] = {r.x, r.y, r.z, r.w};
#pragma unroll
                for (int k = 0; k < 4; k++) {
                    float2 f = __half22float2(*(const __half2*)&rr[k]);
                    h[2 * k]     = f.x;
                    h[2 * k + 1] = f.y;
                }
            }
            int cbase = a * 8;
#pragma unroll
            for (int k = 0; k < 8; k++)
                h[k] = fmaxf(fmaf(h[k], invdeg, sb[cbase + k]), 0.0f);

            float s[L1];
#pragma unroll
            for (int j = 0; j < L1; j++) {
                float acc = 0.0f;
#pragma unroll
                for (int k = 0; k < 8; k++)
                    acc = fmaf(h[k], sl1w[(cbase + k) * L1 + j], acc);
                s[j] = acc;
            }
            float z = 0.0f;
#pragma unroll
            for (int j = 0; j < L1; j++) {
                float sj = s[j] + __shfl_xor_sync(0xFFFFFFFFu, s[j], 1);
                float h2 = fmaxf(sj + sl1b[j], 0.0f);
                z = fmaf(h2, sow[j], z);
            }
            if (a == 0) {
                z += sob[0];
                float p = 1.0f / (1.0f + __expf(-z));
                pout[i] = p;
                const float eps = 1e-7f;
                float pc = fminf(fmaxf(p, eps), 1.0f - eps);
                float sel = (labels[i] > 0.5f) ? pc : (1.0f - pc);  // labels exactly 0/1
                term = wts[i] * (-__logf(sel)) * inv_n;
            }
        }
    }
    // block reduce -> one atomic per block
#pragma unroll
    for (int off = 16; off > 0; off >>= 1)
        term += __shfl_down_sync(0xFFFFFFFFu, term, off);
    int wid = tid >> 5, lid = tid & 31;
    if (lid == 0) wsum[wid] = term;
    __syncthreads();
    if (wid == 0) {
        float s2 = (lid < (NT >> 5)) ? wsum[lid] : 0.0f;
#pragma unroll
        for (int off = 16; off > 0; off >>= 1)
            s2 += __shfl_down_sync(0xFFFFFFFFu, s2, off);
        if (lid == 0 && losss) atomicAdd(losss, s2);
    }
}

// ---------------- launch ----------------
extern "C" void kernel_launch(void* const* d_in, const int* in_sizes, int n_in,
                              void* d_out, int out_size) {
    const float* x      = (const float*)d_in[0];
    const void*  ei     = d_in[1];
    const float* labels = (const float*)d_in[2];
    const float* wts    = (const float*)d_in[3];
    const float* W      = (const float*)d_in[4];
    // d_in[5]=u, d_in[6]=c unused (H=1 softmax == 1)
    const float* bias   = (const float*)d_in[7];
    const float* l1w    = (const float*)d_in[8];
    const float* l1b    = (const float*)d_in[9];
    const float* ow     = (const float*)d_in[10];
    const float* ob     = (const float*)d_in[11];

    int n = in_sizes[0] / FF;
    int E = in_sizes[1] / 2;

    float* out = (float*)d_out;
    int loss_slot = (out_size == n + 1) ? 1 : 0;
    float* pout  = loss_slot ? (out + 1) : out;
    float* losss = loss_slot ? out : (float*)0;

    k_fused<<<NB, NT>>>(x, W, ei, bias, l1w, l1b, ow, ob, labels, wts,
                        pout, losss, n, E, 1.0f / (float)n);
}

// round 10
// speedup vs baseline: 1.0498x; 1.0084x over previous
#include <cuda_runtime.h>
#include <cuda_fp16.h>
#include <math.h>

#define NN 50000
#define FF 48
#define CC 16     // H*C1 with H=1 -> softmax == 1, attention vanishes
#define L1 8

// ---------------- device scratch ----------------
__device__ __align__(32) __half g_yh[NN * CC];    // x @ W (fp16)
__device__ __align__(32) __half g_aggh[NN * CC];  // fp16 segment sum (self loop preloaded)
__device__ int g_degi[NN];   // in-degree; zeroed at load, self-cleaned by k_head

// int64 node ids < 50000 => odd 32-bit words all zero over first 8 entries.
__device__ __forceinline__ bool detect64(const unsigned* __restrict__ ew) {
    unsigned v = 0u;
#pragma unroll
    for (int k = 0; k < 8; k++) v |= __ldg(&ew[2 * k + 1]);
    return v == 0u;
}

__device__ __forceinline__ void red_h8(__half* addr, uint4 v) {
    asm volatile("red.global.add.noftz.v4.f16x2 [%0], {%1,%2,%3,%4};"
                 :: "l"(addr), "r"(v.x), "r"(v.y), "r"(v.z), "r"(v.w) : "memory");
}
__device__ __forceinline__ uint4 ldcg16(const __half* p) {
    uint4 r;
    asm volatile("ld.global.cg.v4.u32 {%0,%1,%2,%3}, [%4];"
                 : "=r"(r.x), "=r"(r.y), "=r"(r.z), "=r"(r.w) : "l"(p));
    return r;
}

// ---------------- fused grid: proj | dst in-degree histogram ----------------
__global__ void k_proj_hist(const float* __restrict__ x, const float* __restrict__ W,
                            const void* __restrict__ ei, float* losss,
                            int n, int E, int projBlocks) {
    int bx = blockIdx.x;
    if (bx < projBlocks) {
        __shared__ float sW[FF * CC];   // 3 KB
        __shared__ float sX[16 * FF];   // 3 KB
        if (bx == 0 && threadIdx.x == 0 && losss) *losss = 0.0f;
        for (int i = threadIdx.x; i < FF * CC; i += blockDim.x) sW[i] = W[i];
        int nodeBase = bx * 16;
        for (int i = threadIdx.x; i < 16 * FF; i += blockDim.x) {
            int g = nodeBase * FF + i;
            sX[i] = (g < n * FF) ? x[g] : 0.0f;
        }
        __syncthreads();
        int node = nodeBase + (threadIdx.x >> 4);
        int c    = threadIdx.x & 15;
        if (node >= n) return;
        const float* xr = &sX[(threadIdx.x >> 4) * FF];
        float acc = 0.0f;
#pragma unroll
        for (int k = 0; k < FF; k++) acc = fmaf(xr[k], sW[k * CC + c], acc);
        __half hv = __float2half(acc);
        g_yh[node * CC + c]   = hv;
        g_aggh[node * CC + c] = hv;     // self-loop contribution
    } else {
        // dst in-degree histogram (g_degi starts at 0 each replay)
        int b = bx - projBlocks;
        int base = b * 1024;            // 4 edges per thread
        if (detect64((const unsigned*)ei)) {
            const long long* dl = (const long long*)ei + E;
#pragma unroll
            for (int k = 0; k < 4; k++) {
                int e = base + k * 256 + threadIdx.x;
                if (e < E) atomicAdd(&g_degi[(int)__ldg(&dl[e])], 1);
            }
        } else {
            const int* dl = (const int*)ei + E;
#pragma unroll
            for (int k = 0; k < 4; k++) {
                int e = base + k * 256 + threadIdx.x;
                if (e < E) atomicAdd(&g_degi[__ldg(&dl[e])], 1);
            }
        }
    }
}

// ---------------- edge scatter: 2 lanes/edge, x2 front-batched ----------------
__global__ void k_edge(const void* __restrict__ ei, int E, int Eh) {
    int t = blockIdx.x * blockDim.x + threadIdx.x;
    int i = t >> 1;                  // edge within first half
    int qo = (t & 1) * 8;            // which 16B half-row
    if (i >= Eh) return;
    int e0 = i, e1 = i + Eh;
    bool h1 = e1 < E;
    int s0, s1 = 0, d0, d1 = 0;
    if (detect64((const unsigned*)ei)) {
        const long long* sp = (const long long*)ei;
        const long long* dp = sp + E;
        s0 = (int)__ldg(&sp[e0]);            d0 = (int)__ldg(&dp[e0]);
        if (h1) { s1 = (int)__ldg(&sp[e1]);  d1 = (int)__ldg(&dp[e1]); }
    } else {
        const int* sp = (const int*)ei;
        const int* dp = sp + E;
        s0 = __ldg(&sp[e0]);            d0 = __ldg(&dp[e0]);
        if (h1) { s1 = __ldg(&sp[e1]);  d1 = __ldg(&dp[e1]); }
    }
    // L2-only loads: y re-use is L2-resident, keep L1 for the idx stream
    uint4 y0 = ldcg16(&g_yh[s0 * CC + qo]);
    uint4 y1 = ldcg16(&g_yh[s1 * CC + qo]);
    red_h8(&g_aggh[d0 * CC + qo], y0);
    if (h1) red_h8(&g_aggh[d1 * CC + qo], y1);
}

// ---------------- head: 2 lanes per node; self-cleans g_degi ----------------
__global__ void k_head(const float* __restrict__ bias,
                       const float* __restrict__ l1w,  // [16,8]
                       const float* __restrict__ l1b,
                       const float* __restrict__ ow,   // [8,1]
                       const float* __restrict__ ob,
                       const float* __restrict__ labels,
                       const float* __restrict__ wts,
                       float* __restrict__ pout, float* losss,
                       int n, float inv_n) {
    __shared__ float sb[CC], sl1w[CC * L1], sl1b[L1], sow[L1], sob;
    if (threadIdx.x < CC) sb[threadIdx.x] = bias[threadIdx.x];
    if (threadIdx.x < CC * L1) sl1w[threadIdx.x] = l1w[threadIdx.x];
    if (threadIdx.x < L1) { sl1b[threadIdx.x] = l1b[threadIdx.x]; sow[threadIdx.x] = ow[threadIdx.x]; }
    if (threadIdx.x == 0) sob = ob[0];
    __syncthreads();

    int t = blockIdx.x * blockDim.x + threadIdx.x;
    int i = t >> 1;            // node
    int a = t & 1;             // which 8-channel half
    float term = 0.0f;
    if (i < n) {
        int degc = __ldg(&g_degi[i]);
        uint4 r = *(const uint4*)&g_aggh[i * CC + a * 8];
        if (a == 0) g_degi[i] = 0;                  // reset for next graph replay
        float invdeg = __fdividef(1.0f, (float)(degc + 1));   // + self loop
        float h[8];
        {
            const unsigned rr[4] = {r.x, r.y, r.z, r.w};
#pragma unroll
            for (int k = 0; k < 4; k++) {
                float2 f = __half22float2(*(const __half2*)&rr[k]);
                h[2 * k]     = f.x;
                h[2 * k + 1] = f.y;
            }
        }
        int cbase = a * 8;
#pragma unroll
        for (int k = 0; k < 8; k++)
            h[k] = fmaxf(fmaf(h[k], invdeg, sb[cbase + k]), 0.0f);

        float s[L1];
#pragma unroll
        for (int j = 0; j < L1; j++) {
            float acc = 0.0f;
#pragma unroll
            for (int k = 0; k < 8; k++)
                acc = fmaf(h[k], sl1w[(cbase + k) * L1 + j], acc);
            s[j] = acc;
        }
        float z = 0.0f;
#pragma unroll
        for (int j = 0; j < L1; j++) {
            float sj = s[j] + __shfl_xor_sync(0xFFFFFFFFu, s[j], 1);
            float h2 = fmaxf(sj + sl1b[j], 0.0f);
            z = fmaf(h2, sow[j], z);
        }
        if (a == 0) {
            z += sob;
            float p = 1.0f / (1.0f + __expf(-z));
            pout[i] = p;
            const float eps = 1e-7f;
            float pc = fminf(fmaxf(p, eps), 1.0f - eps);
            float sel = (labels[i] > 0.5f) ? pc : (1.0f - pc);  // labels exactly 0/1
            term = wts[i] * (-__logf(sel)) * inv_n;
        }
    }
    // block reduce -> one atomic per block
#pragma unroll
    for (int off = 16; off > 0; off >>= 1)
        term += __shfl_down_sync(0xFFFFFFFFu, term, off);
    __shared__ float wsum[8];
    int wid = threadIdx.x >> 5, lid = threadIdx.x & 31;
    if (lid == 0) wsum[wid] = term;
    __syncthreads();
    if (threadIdx.x == 0 && losss) {
        float sum = 0.0f;
#pragma unroll
        for (int k = 0; k < (int)(blockDim.x >> 5); k++) sum += wsum[k];
        atomicAdd(losss, sum);
    }
}

// ---------------- launch ----------------
extern "C" void kernel_launch(void* const* d_in, const int* in_sizes, int n_in,
                              void* d_out, int out_size) {
    const float* x      = (const float*)d_in[0];
    const void*  ei     = d_in[1];
    const float* labels = (const float*)d_in[2];
    const float* wts    = (const float*)d_in[3];
    const float* W      = (const float*)d_in[4];
    // d_in[5]=u, d_in[6]=c unused (H=1 softmax == 1)
    const float* bias   = (const float*)d_in[7];
    const float* l1w    = (const float*)d_in[8];
    const float* l1b    = (const float*)d_in[9];
    const float* ow     = (const float*)d_in[10];
    const float* ob     = (const float*)d_in[11];

    int n = in_sizes[0] / FF;
    int E = in_sizes[1] / 2;

    float* out = (float*)d_out;
    int loss_slot = (out_size == n + 1) ? 1 : 0;
    float* pout  = loss_slot ? (out + 1) : out;
    float* losss = loss_slot ? out : (float*)0;

    int projBlocks = (n + 15) / 16;
    int histBlocks = (E + 1023) / 1024;
    k_proj_hist<<<projBlocks + histBlocks, 256>>>(x, W, ei, losss, n, E, projBlocks);

    int Eh = (E + 1) / 2;
    long long threads = (long long)Eh * 2;
    k_edge<<<(int)((threads + 511) / 512), 512>>>(ei, E, Eh);

    k_head<<<(n * 2 + 255) / 256, 256>>>(bias, l1w, l1b, ow, ob, labels, wts,
                                         pout, losss, n, 1.0f / (float)n);
}

// round 11
// speedup vs baseline: 1.1445x; 1.0902x over previous
#include <cuda_runtime.h>
#include <cuda_fp16.h>
#include <math.h>

#define NN 50000
#define FF 48
#define CC 16     // H*C1 with H=1 -> softmax == 1, attention vanishes
#define L1 8

// ---------------- device scratch ----------------
__device__ __align__(32) __half g_yh[NN * CC];    // x @ W (fp16)
__device__ __align__(32) __half g_aggh[NN * CC];  // fp16 segment sum (self loop preloaded)
__device__ int g_degi[NN];   // in-degree; zeroed at load, self-cleaned by k_head

// int64 node ids < 50000 => odd 32-bit words all zero over first 8 entries.
__device__ __forceinline__ bool detect64(const unsigned* __restrict__ ew) {
    unsigned v = 0u;
#pragma unroll
    for (int k = 0; k < 8; k++) v |= __ldg(&ew[2 * k + 1]);
    return v == 0u;
}

__device__ __forceinline__ void red_h8(__half* addr, uint4 v) {
    asm volatile("red.global.add.noftz.v4.f16x2 [%0], {%1,%2,%3,%4};"
                 :: "l"(addr), "r"(v.x), "r"(v.y), "r"(v.z), "r"(v.w) : "memory");
}

// ---------------- pure projection: y = x @ W (smem-staged) ----------------
__global__ void k_proj(const float* __restrict__ x, const float* __restrict__ W,
                       float* losss, int n) {
    __shared__ float sW[FF * CC];   // 3 KB
    __shared__ float sX[16 * FF];   // 3 KB
    if (blockIdx.x == 0 && threadIdx.x == 0 && losss) *losss = 0.0f;
    for (int i = threadIdx.x; i < FF * CC; i += blockDim.x) sW[i] = W[i];
    int nodeBase = blockIdx.x * 16;
    for (int i = threadIdx.x; i < 16 * FF; i += blockDim.x) {
        int g = nodeBase * FF + i;
        sX[i] = (g < n * FF) ? x[g] : 0.0f;
    }
    __syncthreads();
    int node = nodeBase + (threadIdx.x >> 4);
    int c    = threadIdx.x & 15;
    if (node >= n) return;
    const float* xr = &sX[(threadIdx.x >> 4) * FF];
    float acc = 0.0f;
#pragma unroll
    for (int k = 0; k < FF; k++) acc = fmaf(xr[k], sW[k * CC + c], acc);
    __half hv = __float2half(acc);
    g_yh[node * CC + c]   = hv;
    g_aggh[node * CC + c] = hv;     // self-loop contribution
}

// ---------------- edge scatter: agg REDs + deg RED in ONE kernel ----------------
// 2 lanes per edge (q0/q1 share the y/agg 32B sector), x2 edge batching.
// deg RED issued by the q0 lane only.
__global__ void __launch_bounds__(512) k_edge(const void* __restrict__ ei, int E, int Eh) {
    int t = blockIdx.x * blockDim.x + threadIdx.x;
    int i = t >> 1;                  // edge within first half
    int q0lane = !(t & 1);
    int qo = (t & 1) * 8;            // which 16B half-row
    if (i >= Eh) return;
    int e0 = i, e1 = i + Eh;
    bool h1 = e1 < E;
    int s0, s1 = 0, d0, d1 = 0;
    if (detect64((const unsigned*)ei)) {
        const long long* sp = (const long long*)ei;
        const long long* dp = sp + E;
        s0 = (int)__ldg(&sp[e0]);            d0 = (int)__ldg(&dp[e0]);
        if (h1) { s1 = (int)__ldg(&sp[e1]);  d1 = (int)__ldg(&dp[e1]); }
    } else {
        const int* sp = (const int*)ei;
        const int* dp = sp + E;
        s0 = __ldg(&sp[e0]);            d0 = __ldg(&dp[e0]);
        if (h1) { s1 = __ldg(&sp[e1]);  d1 = __ldg(&dp[e1]); }
    }
    // front-batched independent y loads
    uint4 y0 = __ldg((const uint4*)&g_yh[s0 * CC + qo]);
    uint4 y1 = __ldg((const uint4*)&g_yh[s1 * CC + qo]);
    red_h8(&g_aggh[d0 * CC + qo], y0);
    if (q0lane) atomicAdd(&g_degi[d0], 1);
    if (h1) {
        red_h8(&g_aggh[d1 * CC + qo], y1);
        if (q0lane) atomicAdd(&g_degi[d1], 1);
    }
}

// ---------------- head: 2 lanes per node; self-cleans g_degi ----------------
__global__ void k_head(const float* __restrict__ bias,
                       const float* __restrict__ l1w,  // [16,8]
                       const float* __restrict__ l1b,
                       const float* __restrict__ ow,   // [8,1]
                       const float* __restrict__ ob,
                       const float* __restrict__ labels,
                       const float* __restrict__ wts,
                       float* __restrict__ pout, float* losss,
                       int n, float inv_n) {
    __shared__ float sb[CC], sl1w[CC * L1], sl1b[L1], sow[L1], sob;
    if (threadIdx.x < CC) sb[threadIdx.x] = bias[threadIdx.x];
    if (threadIdx.x < CC * L1) sl1w[threadIdx.x] = l1w[threadIdx.x];
    if (threadIdx.x < L1) { sl1b[threadIdx.x] = l1b[threadIdx.x]; sow[threadIdx.x] = ow[threadIdx.x]; }
    if (threadIdx.x == 0) sob = ob[0];
    __syncthreads();

    int t = blockIdx.x * blockDim.x + threadIdx.x;
    int i = t >> 1;            // node
    int a = t & 1;             // which 8-channel half
    float term = 0.0f;
    if (i < n) {
        int degc = __ldg(&g_degi[i]);
        uint4 r = *(const uint4*)&g_aggh[i * CC + a * 8];
        if (a == 0) g_degi[i] = 0;                  // reset for next graph replay
        float invdeg = __fdividef(1.0f, (float)(degc + 1));   // + self loop
        float h[8];
        {
            const unsigned rr[4] = {r.x, r.y, r.z, r.w};
#pragma unroll
            for (int k = 0; k < 4; k++) {
                float2 f = __half22float2(*(const __half2*)&rr[k]);
                h[2 * k]     = f.x;
                h[2 * k + 1] = f.y;
            }
        }
        int cbase = a * 8;
#pragma unroll
        for (int k = 0; k < 8; k++)
            h[k] = fmaxf(fmaf(h[k], invdeg, sb[cbase + k]), 0.0f);

        float s[L1];
#pragma unroll
        for (int j = 0; j < L1; j++) {
            float acc = 0.0f;
#pragma unroll
            for (int k = 0; k < 8; k++)
                acc = fmaf(h[k], sl1w[(cbase + k) * L1 + j], acc);
            s[j] = acc;
        }
        float z = 0.0f;
#pragma unroll
        for (int j = 0; j < L1; j++) {
            float sj = s[j] + __shfl_xor_sync(0xFFFFFFFFu, s[j], 1);
            float h2 = fmaxf(sj + sl1b[j], 0.0f);
            z = fmaf(h2, sow[j], z);
        }
        if (a == 0) {
            z += sob;
            float p = 1.0f / (1.0f + __expf(-z));
            pout[i] = p;
            const float eps = 1e-7f;
            float pc = fminf(fmaxf(p, eps), 1.0f - eps);
            float sel = (labels[i] > 0.5f) ? pc : (1.0f - pc);  // labels exactly 0/1
            term = wts[i] * (-__logf(sel)) * inv_n;
        }
    }
    // block reduce -> one atomic per block
#pragma unroll
    for (int off = 16; off > 0; off >>= 1)
        term += __shfl_down_sync(0xFFFFFFFFu, term, off);
    __shared__ float wsum[8];
    int wid = threadIdx.x >> 5, lid = threadIdx.x & 31;
    if (lid == 0) wsum[wid] = term;
    __syncthreads();
    if (threadIdx.x == 0 && losss) {
        float sum = 0.0f;
#pragma unroll
        for (int k = 0; k < (int)(blockDim.x >> 5); k++) sum += wsum[k];
        atomicAdd(losss, sum);
    }
}

// ---------------- launch ----------------
extern "C" void kernel_launch(void* const* d_in, const int* in_sizes, int n_in,
                              void* d_out, int out_size) {
    const float* x      = (const float*)d_in[0];
    const void*  ei     = d_in[1];
    const float* labels = (const float*)d_in[2];
    const float* wts    = (const float*)d_in[3];
    const float* W      = (const float*)d_in[4];
    // d_in[5]=u, d_in[6]=c unused (H=1 softmax == 1)
    const float* bias   = (const float*)d_in[7];
    const float* l1w    = (const float*)d_in[8];
    const float* l1b    = (const float*)d_in[9];
    const float* ow     = (const float*)d_in[10];
    const float* ob     = (const float*)d_in[11];

    int n = in_sizes[0] / FF;
    int E = in_sizes[1] / 2;

    float* out = (float*)d_out;
    int loss_slot = (out_size == n + 1) ? 1 : 0;
    float* pout  = loss_slot ? (out + 1) : out;
    float* losss = loss_slot ? out : (float*)0;

    k_proj<<<(n + 15) / 16, 256>>>(x, W, losss, n);

    int Eh = (E + 1) / 2;
    long long threads = (long long)Eh * 2;
    k_edge<<<(int)((threads + 511) / 512), 512>>>(ei, E, Eh);

    k_head<<<(n * 2 + 255) / 256, 256>>>(bias, l1w, l1b, ow, ob, labels, wts,
                                         pout, losss, n, 1.0f / (float)n);
}

// round 12
// speedup vs baseline: 1.2531x; 1.0949x over previous
#include <cuda_runtime.h>
#include <cuda_fp16.h>
#include <math.h>

#define NN 50000
#define FF 48
#define CC 16     // H*C1 with H=1 -> softmax == 1, attention vanishes
#define L1 8

// ---------------- device scratch ----------------
__device__ __align__(32) __half g_yh[NN * CC];    // x @ W (fp16)
__device__ __align__(32) __half g_aggh[NN * CC];  // fp16 segment sum (self loop preloaded)
__device__ int g_degi[NN];   // in-degree; zeroed at load, self-cleaned by k_head

// int64 node ids < 50000 => odd 32-bit words all zero over first 8 entries.
__device__ __forceinline__ bool detect64(const unsigned* __restrict__ ew) {
    unsigned v = 0u;
#pragma unroll
    for (int k = 0; k < 8; k++) v |= __ldg(&ew[2 * k + 1]);
    return v == 0u;
}

__device__ __forceinline__ void red_h8(__half* addr, uint4 v) {
    asm volatile("red.global.add.noftz.v4.f16x2 [%0], {%1,%2,%3,%4};"
                 :: "l"(addr), "r"(v.x), "r"(v.y), "r"(v.z), "r"(v.w) : "memory");
}

// ---------------- projection: y = x @ W, vector/register blocked ----------------
// 256 threads, 64 nodes/block, 4 threads/node, 4 outputs/thread.
// sX padded to 13 float4 per row to avoid 192B-stride bank conflicts.
__global__ void __launch_bounds__(256) k_proj(const float* __restrict__ x,
                                              const float* __restrict__ W,
                                              float* losss, int n) {
    __shared__ float4 sW4[FF * 4];      // 3 KB : W[k][4j..4j+3] at sW4[k*4+j]
    __shared__ float4 sX4[64 * 13];     // 13.3 KB (padded rows)
    if (blockIdx.x == 0 && threadIdx.x == 0 && losss) *losss = 0.0f;

    const int tid = threadIdx.x;
    for (int i = tid; i < FF * 4; i += 256) sW4[i] = ((const float4*)W)[i];

    int nodeBase = blockIdx.x * 64;
    // load 64 rows x 12 float4, coalesced from global
    const float4* Xv = (const float4*)x;
    int vbase = nodeBase * 12;          // 12 float4 per node row
    int vmax  = n * 12;
#pragma unroll
    for (int it = 0; it < 3; it++) {
        int i = it * 256 + tid;         // 0..767
        int row = i / 12, col = i - row * 12;
        float4 v = make_float4(0.f, 0.f, 0.f, 0.f);
        int g = vbase + i;
        if (g < vmax) v = Xv[g];
        sX4[row * 13 + col] = v;
    }
    __syncthreads();

    int ln   = tid >> 2;                // local node 0..63
    int jq   = tid & 3;                 // which c-quad (c = 4*jq .. 4*jq+3)
    int node = nodeBase + ln;
    if (node >= n) return;

    float a0 = 0.f, a1 = 0.f, a2 = 0.f, a3 = 0.f;
    const float4* xr = &sX4[ln * 13];
#pragma unroll
    for (int c4 = 0; c4 < 12; c4++) {
        float4 xv = xr[c4];
        int k = c4 * 4;
        float4 w0 = sW4[(k + 0) * 4 + jq];
        float4 w1 = sW4[(k + 1) * 4 + jq];
        float4 w2 = sW4[(k + 2) * 4 + jq];
        float4 w3 = sW4[(k + 3) * 4 + jq];
        a0 = fmaf(xv.x, w0.x, a0); a1 = fmaf(xv.x, w0.y, a1);
        a2 = fmaf(xv.x, w0.z, a2); a3 = fmaf(xv.x, w0.w, a3);
        a0 = fmaf(xv.y, w1.x, a0); a1 = fmaf(xv.y, w1.y, a1);
        a2 = fmaf(xv.y, w1.z, a2); a3 = fmaf(xv.y, w1.w, a3);
        a0 = fmaf(xv.z, w2.x, a0); a1 = fmaf(xv.z, w2.y, a1);
        a2 = fmaf(xv.z, w2.z, a2); a3 = fmaf(xv.z, w2.w, a3);
        a0 = fmaf(xv.w, w3.x, a0); a1 = fmaf(xv.w, w3.y, a1);
        a2 = fmaf(xv.w, w3.z, a2); a3 = fmaf(xv.w, w3.w, a3);
    }
    __half2 h01 = __floats2half2_rn(a0, a1);
    __half2 h23 = __floats2half2_rn(a2, a3);
    uint2 pack;
    pack.x = *(unsigned*)&h01;
    pack.y = *(unsigned*)&h23;
    *(uint2*)&g_yh[node * CC + jq * 4]   = pack;
    *(uint2*)&g_aggh[node * CC + jq * 4] = pack;   // self-loop contribution
}

// ---------------- edge scatter: agg REDs + deg RED in ONE kernel ----------------
// 2 lanes per edge (q0/q1 share the y/agg 32B sector), x2 edge batching.
// deg RED issued by the q0 lane only.
__global__ void __launch_bounds__(512) k_edge(const void* __restrict__ ei, int E, int Eh) {
    int t = blockIdx.x * blockDim.x + threadIdx.x;
    int i = t >> 1;                  // edge within first half
    int q0lane = !(t & 1);
    int qo = (t & 1) * 8;            // which 16B half-row
    if (i >= Eh) return;
    int e0 = i, e1 = i + Eh;
    bool h1 = e1 < E;
    int s0, s1 = 0, d0, d1 = 0;
    if (detect64((const unsigned*)ei)) {
        const long long* sp = (const long long*)ei;
        const long long* dp = sp + E;
        s0 = (int)__ldg(&sp[e0]);            d0 = (int)__ldg(&dp[e0]);
        if (h1) { s1 = (int)__ldg(&sp[e1]);  d1 = (int)__ldg(&dp[e1]); }
    } else {
        const int* sp = (const int*)ei;
        const int* dp = sp + E;
        s0 = __ldg(&sp[e0]);            d0 = __ldg(&dp[e0]);
        if (h1) { s1 = __ldg(&sp[e1]);  d1 = __ldg(&dp[e1]); }
    }
    // front-batched independent y loads
    uint4 y0 = __ldg((const uint4*)&g_yh[s0 * CC + qo]);
    uint4 y1 = __ldg((const uint4*)&g_yh[s1 * CC + qo]);
    red_h8(&g_aggh[d0 * CC + qo], y0);
    if (q0lane) atomicAdd(&g_degi[d0], 1);
    if (h1) {
        red_h8(&g_aggh[d1 * CC + qo], y1);
        if (q0lane) atomicAdd(&g_degi[d1], 1);
    }
}

// ---------------- head: 2 lanes per node; self-cleans g_degi ----------------
__global__ void k_head(const float* __restrict__ bias,
                       const float* __restrict__ l1w,  // [16,8]
                       const float* __restrict__ l1b,
                       const float* __restrict__ ow,   // [8,1]
                       const float* __restrict__ ob,
                       const float* __restrict__ labels,
                       const float* __restrict__ wts,
                       float* __restrict__ pout, float* losss,
                       int n, float inv_n) {
    __shared__ float sb[CC], sl1w[CC * L1], sl1b[L1], sow[L1], sob;
    if (threadIdx.x < CC) sb[threadIdx.x] = bias[threadIdx.x];
    if (threadIdx.x < CC * L1) sl1w[threadIdx.x] = l1w[threadIdx.x];
    if (threadIdx.x < L1) { sl1b[threadIdx.x] = l1b[threadIdx.x]; sow[threadIdx.x] = ow[threadIdx.x]; }
    if (threadIdx.x == 0) sob = ob[0];
    __syncthreads();

    int t = blockIdx.x * blockDim.x + threadIdx.x;
    int i = t >> 1;            // node
    int a = t & 1;             // which 8-channel half
    float term = 0.0f;
    if (i < n) {
        int degc = __ldg(&g_degi[i]);
        uint4 r = *(const uint4*)&g_aggh[i * CC + a * 8];
        if (a == 0) g_degi[i] = 0;                  // reset for next graph replay
        float invdeg = __fdividef(1.0f, (float)(degc + 1));   // + self loop
        float h[8];
        {
            const unsigned rr[4] = {r.x, r.y, r.z, r.w};
#pragma unroll
            for (int k = 0; k < 4; k++) {
                float2 f = __half22float2(*(const __half2*)&rr[k]);
                h[2 * k]     = f.x;
                h[2 * k + 1] = f.y;
            }
        }
        int cbase = a * 8;
#pragma unroll
        for (int k = 0; k < 8; k++)
            h[k] = fmaxf(fmaf(h[k], invdeg, sb[cbase + k]), 0.0f);

        float s[L1];
#pragma unroll
        for (int j = 0; j < L1; j++) {
            float acc = 0.0f;
#pragma unroll
            for (int k = 0; k < 8; k++)
                acc = fmaf(h[k], sl1w[(cbase + k) * L1 + j], acc);
            s[j] = acc;
        }
        float z = 0.0f;
#pragma unroll
        for (int j = 0; j < L1; j++) {
            float sj = s[j] + __shfl_xor_sync(0xFFFFFFFFu, s[j], 1);
            float h2 = fmaxf(sj + sl1b[j], 0.0f);
            z = fmaf(h2, sow[j], z);
        }
        if (a == 0) {
            z += sob;
            float p = 1.0f / (1.0f + __expf(-z));
            pout[i] = p;
            const float eps = 1e-7f;
            float pc = fminf(fmaxf(p, eps), 1.0f - eps);
            float sel = (labels[i] > 0.5f) ? pc : (1.0f - pc);  // labels exactly 0/1
            term = wts[i] * (-__logf(sel)) * inv_n;
        }
    }
    // block reduce -> one atomic per block
#pragma unroll
    for (int off = 16; off > 0; off >>= 1)
        term += __shfl_down_sync(0xFFFFFFFFu, term, off);
    __shared__ float wsum[8];
    int wid = threadIdx.x >> 5, lid = threadIdx.x & 31;
    if (lid == 0) wsum[wid] = term;
    __syncthreads();
    if (threadIdx.x == 0 && losss) {
        float sum = 0.0f;
#pragma unroll
        for (int k = 0; k < (int)(blockDim.x >> 5); k++) sum += wsum[k];
        atomicAdd(losss, sum);
    }
}

// ---------------- launch ----------------
extern "C" void kernel_launch(void* const* d_in, const int* in_sizes, int n_in,
                              void* d_out, int out_size) {
    const float* x      = (const float*)d_in[0];
    const void*  ei     = d_in[1];
    const float* labels = (const float*)d_in[2];
    const float* wts    = (const float*)d_in[3];
    const float* W      = (const float*)d_in[4];
    // d_in[5]=u, d_in[6]=c unused (H=1 softmax == 1)
    const float* bias   = (const float*)d_in[7];
    const float* l1w    = (const float*)d_in[8];
    const float* l1b    = (const float*)d_in[9];
    const float* ow     = (const float*)d_in[10];
    const float* ob     = (const float*)d_in[11];

    int n = in_sizes[0] / FF;
    int E = in_sizes[1] / 2;

    float* out = (float*)d_out;
    int loss_slot = (out_size == n + 1) ? 1 : 0;
    float* pout  = loss_slot ? (out + 1) : out;
    float* losss = loss_slot ? out : (float*)0;

    k_proj<<<(n + 63) / 64, 256>>>(x, W, losss, n);

    int Eh = (E + 1) / 2;
    long long threads = (long long)Eh * 2;
    k_edge<<<(int)((threads + 511) / 512), 512>>>(ei, E, Eh);

    k_head<<<(n * 2 + 255) / 256, 256>>>(bias, l1w, l1b, ow, ob, labels, wts,
                                         pout, losss, n, 1.0f / (float)n);
}

// round 13
// speedup vs baseline: 1.2668x; 1.0109x over previous
#include <cuda_runtime.h>
#include <cuda_fp16.h>
#include <math.h>

#define NN 50000
#define FF 48
#define CC 16     // H*C1 with H=1 -> softmax == 1, attention vanishes
#define L1 8

// ---------------- device scratch ----------------
__device__ __align__(32) __half g_yh[NN * CC];    // x @ W (fp16)
__device__ __align__(32) __half g_aggh[NN * CC];  // fp16 segment sum (self loop preloaded)
__device__ int g_degi[NN];   // in-degree; zeroed at load, self-cleaned by k_head
__device__ int g_is64;       // edge dtype flag, written by k_proj each run

// int64 node ids < 50000 => odd 32-bit words all zero over first 8 entries.
__device__ __forceinline__ bool detect64(const unsigned* __restrict__ ew) {
    unsigned v = 0u;
#pragma unroll
    for (int k = 0; k < 8; k++) v |= __ldg(&ew[2 * k + 1]);
    return v == 0u;
}

__device__ __forceinline__ void red_h8(__half* addr, uint4 v) {
    asm volatile("red.global.add.noftz.v4.f16x2 [%0], {%1,%2,%3,%4};"
                 :: "l"(addr), "r"(v.x), "r"(v.y), "r"(v.z), "r"(v.w) : "memory");
}

// ---------------- projection: y = x @ W, vector/register blocked ----------------
// 256 threads, 64 nodes/block, 4 threads/node, 4 outputs/thread.
// sX padded to 13 float4 per row to avoid 192B-stride bank conflicts.
__global__ void __launch_bounds__(256) k_proj(const float* __restrict__ x,
                                              const float* __restrict__ W,
                                              const void* __restrict__ ei,
                                              float* losss, int n) {
    __shared__ float4 sW4[FF * 4];      // 3 KB : W[k][4j..4j+3] at sW4[k*4+j]
    __shared__ float4 sX4[64 * 13];     // 13.3 KB (padded rows)
    if (blockIdx.x == 0 && threadIdx.x == 0) {
        if (losss) *losss = 0.0f;
        g_is64 = detect64((const unsigned*)ei) ? 1 : 0;
    }

    const int tid = threadIdx.x;
    for (int i = tid; i < FF * 4; i += 256) sW4[i] = ((const float4*)W)[i];

    int nodeBase = blockIdx.x * 64;
    const float4* Xv = (const float4*)x;
    int vbase = nodeBase * 12;          // 12 float4 per node row
    int vmax  = n * 12;
#pragma unroll
    for (int it = 0; it < 3; it++) {
        int i = it * 256 + tid;         // 0..767
        int row = i / 12, col = i - row * 12;
        float4 v = make_float4(0.f, 0.f, 0.f, 0.f);
        int g = vbase + i;
        if (g < vmax) v = Xv[g];
        sX4[row * 13 + col] = v;
    }
    __syncthreads();

    int ln   = tid >> 2;                // local node 0..63
    int jq   = tid & 3;                 // which c-quad (c = 4*jq .. 4*jq+3)
    int node = nodeBase + ln;
    if (node >= n) return;

    float a0 = 0.f, a1 = 0.f, a2 = 0.f, a3 = 0.f;
    const float4* xr = &sX4[ln * 13];
#pragma unroll
    for (int c4 = 0; c4 < 12; c4++) {
        float4 xv = xr[c4];
        int k = c4 * 4;
        float4 w0 = sW4[(k + 0) * 4 + jq];
        float4 w1 = sW4[(k + 1) * 4 + jq];
        float4 w2 = sW4[(k + 2) * 4 + jq];
        float4 w3 = sW4[(k + 3) * 4 + jq];
        a0 = fmaf(xv.x, w0.x, a0); a1 = fmaf(xv.x, w0.y, a1);
        a2 = fmaf(xv.x, w0.z, a2); a3 = fmaf(xv.x, w0.w, a3);
        a0 = fmaf(xv.y, w1.x, a0); a1 = fmaf(xv.y, w1.y, a1);
        a2 = fmaf(xv.y, w1.z, a2); a3 = fmaf(xv.y, w1.w, a3);
        a0 = fmaf(xv.z, w2.x, a0); a1 = fmaf(xv.z, w2.y, a1);
        a2 = fmaf(xv.z, w2.z, a2); a3 = fmaf(xv.z, w2.w, a3);
        a0 = fmaf(xv.w, w3.x, a0); a1 = fmaf(xv.w, w3.y, a1);
        a2 = fmaf(xv.w, w3.z, a2); a3 = fmaf(xv.w, w3.w, a3);
    }
    __half2 h01 = __floats2half2_rn(a0, a1);
    __half2 h23 = __floats2half2_rn(a2, a3);
    uint2 pack;
    pack.x = *(unsigned*)&h01;
    pack.y = *(unsigned*)&h23;
    *(uint2*)&g_yh[node * CC + jq * 4]   = pack;
    *(uint2*)&g_aggh[node * CC + jq * 4] = pack;   // self-loop contribution
}

// ---------------- edge scatter: consecutive-edge pairs, vector idx loads ----------------
// thread t: pair = t>>1 (edges 2p, 2p+1), q = t&1 (which 16B half-row).
// Both q-lanes of a pair load the same idx vector (broadcast). deg REDs on q0.
__global__ void __launch_bounds__(512) k_edge(const void* __restrict__ ei, int E) {
    int t = blockIdx.x * blockDim.x + threadIdx.x;
    int p = t >> 1;
    int e0 = 2 * p, e1 = 2 * p + 1;
    if (e0 >= E) return;
    bool h1 = e1 < E;
    int q0lane = !(t & 1);
    int qo = (t & 1) * 8;

    int s0, s1 = 0, d0, d1 = 0;
    if (g_is64) {
        const uint4* sp = (const uint4*)ei;                 // 2 int64 per uint4
        const long long* base = (const long long*)ei;
        uint4 sv = __ldg(&sp[p]);
        s0 = (int)sv.x; s1 = (int)sv.z;
        const uint4* dp = (const uint4*)(base + E);
        if ((E & 1) == 0) {
            uint4 dv = __ldg(&dp[p]);
            d0 = (int)dv.x; d1 = (int)dv.z;
        } else {                                            // unaligned fallback
            d0 = (int)__ldg(&base[E + e0]);
            if (h1) d1 = (int)__ldg(&base[E + e1]);
        }
    } else {
        const int2* sp = (const int2*)ei;
        const int* base = (const int*)ei;
        int2 sv = __ldg(&sp[p]);
        s0 = sv.x; s1 = sv.y;
        if ((E & 1) == 0) {
            int2 dv = __ldg((const int2*)(base + E) + p);
            d0 = dv.x; d1 = dv.y;
        } else {
            d0 = __ldg(&base[E + e0]);
            if (h1) d1 = __ldg(&base[E + e1]);
        }
    }
    // front-batched independent y loads
    uint4 y0 = __ldg((const uint4*)&g_yh[s0 * CC + qo]);
    uint4 y1 = __ldg((const uint4*)&g_yh[s1 * CC + qo]);
    red_h8(&g_aggh[d0 * CC + qo], y0);
    if (q0lane) atomicAdd(&g_degi[d0], 1);
    if (h1) {
        red_h8(&g_aggh[d1 * CC + qo], y1);
        if (q0lane) atomicAdd(&g_degi[d1], 1);
    }
}

// ---------------- head: 2 lanes per node; self-cleans g_degi ----------------
__global__ void k_head(const float* __restrict__ bias,
                       const float* __restrict__ l1w,  // [16,8]
                       const float* __restrict__ l1b,
                       const float* __restrict__ ow,   // [8,1]
                       const float* __restrict__ ob,
                       const float* __restrict__ labels,
                       const float* __restrict__ wts,
                       float* __restrict__ pout, float* losss,
                       int n, float inv_n) {
    __shared__ float sb[CC], sl1w[CC * L1], sl1b[L1], sow[L1], sob;
    if (threadIdx.x < CC) sb[threadIdx.x] = bias[threadIdx.x];
    if (threadIdx.x < CC * L1) sl1w[threadIdx.x] = l1w[threadIdx.x];
    if (threadIdx.x < L1) { sl1b[threadIdx.x] = l1b[threadIdx.x]; sow[threadIdx.x] = ow[threadIdx.x]; }
    if (threadIdx.x == 0) sob = ob[0];
    __syncthreads();

    int t = blockIdx.x * blockDim.x + threadIdx.x;
    int i = t >> 1;            // node
    int a = t & 1;             // which 8-channel half
    float term = 0.0f;
    if (i < n) {
        int degc = __ldg(&g_degi[i]);
        uint4 r = *(const uint4*)&g_aggh[i * CC + a * 8];
        if (a == 0) g_degi[i] = 0;                  // reset for next graph replay
        float invdeg = __fdividef(1.0f, (float)(degc + 1));   // + self loop
        float h[8];
        {
            const unsigned rr[4] = {r.x, r.y, r.z, r.w};
#pragma unroll
            for (int k = 0; k < 4; k++) {
                float2 f = __half22float2(*(const __half2*)&rr[k]);
                h[2 * k]     = f.x;
                h[2 * k + 1] = f.y;
            }
        }
        int cbase = a * 8;
#pragma unroll
        for (int k = 0; k < 8; k++)
            h[k] = fmaxf(fmaf(h[k], invdeg, sb[cbase + k]), 0.0f);

        float s[L1];
#pragma unroll
        for (int j = 0; j < L1; j++) {
            float acc = 0.0f;
#pragma unroll
            for (int k = 0; k < 8; k++)
                acc = fmaf(h[k], sl1w[(cbase + k) * L1 + j], acc);
            s[j] = acc;
        }
        float z = 0.0f;
#pragma unroll
        for (int j = 0; j < L1; j++) {
            float sj = s[j] + __shfl_xor_sync(0xFFFFFFFFu, s[j], 1);
            float h2 = fmaxf(sj + sl1b[j], 0.0f);
            z = fmaf(h2, sow[j], z);
        }
        if (a == 0) {
            z += sob;
            float p = 1.0f / (1.0f + __expf(-z));
            pout[i] = p;
            const float eps = 1e-7f;
            float pc = fminf(fmaxf(p, eps), 1.0f - eps);
            float sel = (labels[i] > 0.5f) ? pc : (1.0f - pc);  // labels exactly 0/1
            term = wts[i] * (-__logf(sel)) * inv_n;
        }
    }
    // block reduce -> one atomic per block
#pragma unroll
    for (int off = 16; off > 0; off >>= 1)
        term += __shfl_down_sync(0xFFFFFFFFu, term, off);
    __shared__ float wsum[8];
    int wid = threadIdx.x >> 5, lid = threadIdx.x & 31;
    if (lid == 0) wsum[wid] = term;
    __syncthreads();
    if (threadIdx.x == 0 && losss) {
        float sum = 0.0f;
#pragma unroll
        for (int k = 0; k < (int)(blockDim.x >> 5); k++) sum += wsum[k];
        atomicAdd(losss, sum);
    }
}

// ---------------- launch ----------------
extern "C" void kernel_launch(void* const* d_in, const int* in_sizes, int n_in,
                              void* d_out, int out_size) {
    const float* x      = (const float*)d_in[0];
    const void*  ei     = d_in[1];
    const float* labels = (const float*)d_in[2];
    const float* wts    = (const float*)d_in[3];
    const float* W      = (const float*)d_in[4];
    // d_in[5]=u, d_in[6]=c unused (H=1 softmax == 1)
    const float* bias   = (const float*)d_in[7];
    const float* l1w    = (const float*)d_in[8];
    const float* l1b    = (const float*)d_in[9];
    const float* ow     = (const float*)d_in[10];
    const float* ob     = (const float*)d_in[11];

    int n = in_sizes[0] / FF;
    int E = in_sizes[1] / 2;

    float* out = (float*)d_out;
    int loss_slot = (out_size == n + 1) ? 1 : 0;
    float* pout  = loss_slot ? (out + 1) : out;
    float* losss = loss_slot ? out : (float*)0;

    k_proj<<<(n + 63) / 64, 256>>>(x, W, ei, losss, n);

    long long threads = ((long long)E + 1) / 2 * 2;   // 2 threads per edge pair
    k_edge<<<(int)((threads + 511) / 512), 512>>>(ei, E);

    k_head<<<(n * 2 + 255) / 256, 256>>>(bias, l1w, l1b, ow, ob, labels, wts,
                                         pout, losss, n, 1.0f / (float)n);
}